// round 3
// baseline (speedup 1.0000x reference)
#include <cuda_runtime.h>

#define N_NODES 300000
#define DIM 128
#define KNBR 5
#define EPS_LN 1e-5f
#define BLOCK 64
#define NTHREADS 512
#define NTILES ((N_NODES + BLOCK - 1) / BLOCK)

// ---------------- global scratch (static device allocations) ----------------
__device__ float g_Kp1[(size_t)N_NODES * DIM];
__device__ float g_Vp1[(size_t)N_NODES * DIM];
__device__ float g_Kp2[(size_t)N_NODES * DIM];
__device__ float g_Vp2[(size_t)N_NODES * DIM];
__device__ float g_rowsum[N_NODES];

// ---------------- shared memory layouts ----------------
struct SmemMain {
    float X[BLOCK * DIM];        // residual stream (64 x 128)
    float T[BLOCK * 256];        // q1 / attn out / ffn hidden (64 x 256)
    float U[BLOCK * DIM];        // pre-LN gemm outputs (64 x 128)
    float W[DIM * DIM];          // current weight tile (128 x 128)
    int   nidx[BLOCK * KNBR];
    int   nmask[BLOCK * KNBR];
};

struct SmemPre {
    float X[BLOCK * DIM];
    float W[DIM * DIM];
};

// ---------------- helpers ----------------

// Copy a 128x128 weight tile from global (row0, col0) of a (?, ncols) matrix.
__device__ __forceinline__ void load_w(const float* __restrict__ Wg,
                                       int row0, int col0, int ncols,
                                       float* __restrict__ Ws) {
    int tid = threadIdx.x;
    #pragma unroll
    for (int i = tid; i < DIM * (DIM / 4); i += NTHREADS) {   // 4096 float4
        int r  = i >> 5;
        int c4 = (i & 31) << 2;
        *(float4*)(Ws + r * DIM + c4) =
            *(const float4*)(Wg + (size_t)(row0 + r) * ncols + col0 + c4);
    }
}

// C(64 x 128) += A(64 x 128-chunk) @ Ws(128 x 128). Thread owns 2 rows x 8 cols.
__device__ __forceinline__ void gemm_tile(const float* __restrict__ A, int lda, int aoff,
                                          const float* __restrict__ Ws,
                                          int r0, int c0, float acc[16]) {
    const float* a0p = A + r0 * lda + aoff;
    const float* a1p = a0p + lda;
    #pragma unroll 8
    for (int kk = 0; kk < DIM; ++kk) {
        float a0 = a0p[kk];
        float a1 = a1p[kk];
        float4 w0 = *(const float4*)(Ws + kk * DIM + c0);
        float4 w1 = *(const float4*)(Ws + kk * DIM + c0 + 4);
        acc[0]  = fmaf(a0, w0.x, acc[0]);
        acc[1]  = fmaf(a0, w0.y, acc[1]);
        acc[2]  = fmaf(a0, w0.z, acc[2]);
        acc[3]  = fmaf(a0, w0.w, acc[3]);
        acc[4]  = fmaf(a0, w1.x, acc[4]);
        acc[5]  = fmaf(a0, w1.y, acc[5]);
        acc[6]  = fmaf(a0, w1.z, acc[6]);
        acc[7]  = fmaf(a0, w1.w, acc[7]);
        acc[8]  = fmaf(a1, w0.x, acc[8]);
        acc[9]  = fmaf(a1, w0.y, acc[9]);
        acc[10] = fmaf(a1, w0.z, acc[10]);
        acc[11] = fmaf(a1, w0.w, acc[11]);
        acc[12] = fmaf(a1, w1.x, acc[12]);
        acc[13] = fmaf(a1, w1.y, acc[13]);
        acc[14] = fmaf(a1, w1.z, acc[14]);
        acc[15] = fmaf(a1, w1.w, acc[15]);
    }
}

__device__ __forceinline__ void zero_acc(float acc[16]) {
    #pragma unroll
    for (int i = 0; i < 16; ++i) acc[i] = 0.f;
}

// X = LN(X + U) * gamma + beta, per row (128). 8 threads per row.
__device__ __forceinline__ void layernorm_inplace(float* __restrict__ Xs,
                                                  const float* __restrict__ Us,
                                                  const float* __restrict__ gamma,
                                                  const float* __restrict__ beta) {
    int tid  = threadIdx.x;
    int node = tid >> 3;
    int h    = tid & 7;
    float*       xp = Xs + node * DIM + h * 16;
    const float* up = Us + node * DIM + h * 16;
    float v[16];
    float sum = 0.f;
    #pragma unroll
    for (int i = 0; i < 16; ++i) { v[i] = xp[i] + up[i]; sum += v[i]; }
    sum += __shfl_xor_sync(0xffffffffu, sum, 1);
    sum += __shfl_xor_sync(0xffffffffu, sum, 2);
    sum += __shfl_xor_sync(0xffffffffu, sum, 4);
    float m = sum * (1.f / 128.f);
    float sq = 0.f;
    #pragma unroll
    for (int i = 0; i < 16; ++i) { float d = v[i] - m; sq = fmaf(d, d, sq); }
    sq += __shfl_xor_sync(0xffffffffu, sq, 1);
    sq += __shfl_xor_sync(0xffffffffu, sq, 2);
    sq += __shfl_xor_sync(0xffffffffu, sq, 4);
    float inv = rsqrtf(sq * (1.f / 128.f) + EPS_LN);
    #pragma unroll
    for (int i = 0; i < 16; ++i)
        xp[i] = (v[i] - m) * inv * gamma[h * 16 + i] + beta[h * 16 + i];
}

// ---------------- one transformer layer (fused, per CTA tile) ----------------
__device__ void run_layer(SmemMain* s, int base,
                          const float* wq, const float* wo, const float* bo,
                          const float* wa, const float* ba,
                          const float* wb, const float* bb,
                          const float* ga, const float* bea,
                          const float* gb, const float* beb,
                          const float* __restrict__ Kp,
                          const float* __restrict__ Vp) {
    int tid = threadIdx.x;
    int rg = tid >> 4;             // 0..31
    int cg = tid & 15;             // 0..15
    int r0 = rg * 2, c0 = cg * 8;
    float acc[16];

    // ---- 1. Q1 = X @ wq -> T[:, 0:128] ----
    load_w(wq, 0, 0, DIM, s->W);
    __syncthreads();
    zero_acc(acc);
    gemm_tile(s->X, DIM, 0, s->W, r0, c0, acc);
    #pragma unroll
    for (int rr = 0; rr < 2; ++rr)
        #pragma unroll
        for (int c = 0; c < 8; ++c)
            s->T[(r0 + rr) * 256 + c0 + c] = acc[rr * 8 + c];
    __syncthreads();

    // ---- 2. attention: 8 threads per node, one head each ----
    {
        int node = tid >> 3;
        int h    = tid & 7;
        int g    = base + node;
        if (g < N_NODES) {
            float* qs = s->T + node * 256 + h * 16;
            float q[16];
            #pragma unroll
            for (int i = 0; i < 16; ++i) q[i] = qs[i];

            float dots[KNBR];
            bool  msk[KNBR];
            #pragma unroll
            for (int j = 0; j < KNBR; ++j) {
                int mflag = s->nmask[node * KNBR + j];
                msk[j] = (mflag != 0);
                if (mflag) { dots[j] = -1e30f; continue; }
                int idx = s->nidx[node * KNBR + j];
                const float4* kp = (const float4*)(Kp + (size_t)idx * DIM + h * 16);
                float d = 0.f;
                #pragma unroll
                for (int t = 0; t < 4; ++t) {
                    float4 k4 = kp[t];
                    d = fmaf(q[4*t+0], k4.x, d);
                    d = fmaf(q[4*t+1], k4.y, d);
                    d = fmaf(q[4*t+2], k4.z, d);
                    d = fmaf(q[4*t+3], k4.w, d);
                }
                dots[j] = d * 0.25f;   // dh^-0.5, dh=16
            }
            float mmax = -1e30f;
            #pragma unroll
            for (int j = 0; j < KNBR; ++j) mmax = fmaxf(mmax, dots[j]);
            float e[KNBR]; float ssum = 0.f;
            #pragma unroll
            for (int j = 0; j < KNBR; ++j) {
                e[j] = msk[j] ? 0.f : __expf(dots[j] - mmax);
                ssum += e[j];
            }
            float inv = 1.f / ssum;
            float4 o[4];
            #pragma unroll
            for (int t = 0; t < 4; ++t) o[t] = make_float4(0.f, 0.f, 0.f, 0.f);
            #pragma unroll
            for (int j = 0; j < KNBR; ++j) {
                if (!msk[j]) {
                    int idx = s->nidx[node * KNBR + j];
                    const float4* vp = (const float4*)(Vp + (size_t)idx * DIM + h * 16);
                    float a = e[j] * inv;
                    #pragma unroll
                    for (int t = 0; t < 4; ++t) {
                        float4 v4 = vp[t];
                        o[t].x = fmaf(a, v4.x, o[t].x);
                        o[t].y = fmaf(a, v4.y, o[t].y);
                        o[t].z = fmaf(a, v4.z, o[t].z);
                        o[t].w = fmaf(a, v4.w, o[t].w);
                    }
                }
            }
            #pragma unroll
            for (int t = 0; t < 4; ++t) ((float4*)qs)[t] = o[t];
        }
    }
    __syncthreads();

    // ---- 3. AO = T[:,0:128] @ wo + bo -> U ----
    load_w(wo, 0, 0, DIM, s->W);
    __syncthreads();
    zero_acc(acc);
    gemm_tile(s->T, 256, 0, s->W, r0, c0, acc);
    #pragma unroll
    for (int rr = 0; rr < 2; ++rr)
        #pragma unroll
        for (int c = 0; c < 8; ++c)
            s->U[(r0 + rr) * DIM + c0 + c] = acc[rr * 8 + c] + bo[c0 + c];
    __syncthreads();

    // ---- 4. X = LN(X + U) ----
    layernorm_inplace(s->X, s->U, ga, bea);
    __syncthreads();

    // ---- 5. H = relu(X @ wa + ba) -> T (64 x 256), two col halves ----
    #pragma unroll
    for (int half = 0; half < 2; ++half) {
        load_w(wa, 0, half * 128, 256, s->W);
        __syncthreads();
        zero_acc(acc);
        gemm_tile(s->X, DIM, 0, s->W, r0, c0, acc);
        #pragma unroll
        for (int rr = 0; rr < 2; ++rr)
            #pragma unroll
            for (int c = 0; c < 8; ++c)
                s->T[(r0 + rr) * 256 + half * 128 + c0 + c] =
                    fmaxf(acc[rr * 8 + c] + ba[half * 128 + c0 + c], 0.f);
        __syncthreads();
    }

    // ---- 6. F = T(64x256) @ wb + bb -> U, two K halves ----
    zero_acc(acc);
    load_w(wb, 0, 0, DIM, s->W);
    __syncthreads();
    gemm_tile(s->T, 256, 0, s->W, r0, c0, acc);
    __syncthreads();
    load_w(wb, 128, 0, DIM, s->W);
    __syncthreads();
    gemm_tile(s->T, 256, 128, s->W, r0, c0, acc);
    #pragma unroll
    for (int rr = 0; rr < 2; ++rr)
        #pragma unroll
        for (int c = 0; c < 8; ++c)
            s->U[(r0 + rr) * DIM + c0 + c] = acc[rr * 8 + c] + bb[c0 + c];
    __syncthreads();

    // ---- 7. X = LN(X + U) ----
    layernorm_inplace(s->X, s->U, gb, beb);
    __syncthreads();
}

// ---------------- kernel 1: precompute Kp/Vp projections + row sums ----------------
extern "C" __global__ void __launch_bounds__(NTHREADS)
pre_kernel(const float* __restrict__ feat,
           const float* __restrict__ wk1, const float* __restrict__ wv1,
           const float* __restrict__ wk2, const float* __restrict__ wv2) {
    extern __shared__ char smem_raw[];
    SmemPre* s = (SmemPre*)smem_raw;
    int tid  = threadIdx.x;
    int base = blockIdx.x * BLOCK;

    // load X tile (zero-padded)
    #pragma unroll
    for (int i = tid; i < BLOCK * (DIM / 4); i += NTHREADS) {
        int node = i >> 5;
        int c4   = (i & 31) << 2;
        int g    = base + node;
        float4 v = make_float4(0.f, 0.f, 0.f, 0.f);
        if (g < N_NODES) v = *(const float4*)(feat + (size_t)g * DIM + c4);
        *(float4*)(s->X + node * DIM + c4) = v;
    }
    __syncthreads();

    // row sums (for the mask)
    {
        int node = tid >> 3;
        int h    = tid & 7;
        float ssum = 0.f;
        #pragma unroll
        for (int i = 0; i < 16; ++i) ssum += s->X[node * DIM + h * 16 + i];
        ssum += __shfl_xor_sync(0xffffffffu, ssum, 1);
        ssum += __shfl_xor_sync(0xffffffffu, ssum, 2);
        ssum += __shfl_xor_sync(0xffffffffu, ssum, 4);
        int g = base + node;
        if (h == 0 && g < N_NODES) g_rowsum[g] = ssum;
    }

    int rg = tid >> 4, cg = tid & 15;
    int r0 = rg * 2, c0 = cg * 8;
    const float* ws_in[4] = {wk1, wv1, wk2, wv2};
    float* outs[4] = {g_Kp1, g_Vp1, g_Kp2, g_Vp2};
    float acc[16];
    #pragma unroll
    for (int w = 0; w < 4; ++w) {
        load_w(ws_in[w], 0, 0, DIM, s->W);
        __syncthreads();
        zero_acc(acc);
        gemm_tile(s->X, DIM, 0, s->W, r0, c0, acc);
        #pragma unroll
        for (int rr = 0; rr < 2; ++rr) {
            int g = base + r0 + rr;
            if (g < N_NODES) {
                float* op = outs[w] + (size_t)g * DIM + c0;
                *(float4*)(op)     = make_float4(acc[rr*8+0], acc[rr*8+1], acc[rr*8+2], acc[rr*8+3]);
                *(float4*)(op + 4) = make_float4(acc[rr*8+4], acc[rr*8+5], acc[rr*8+6], acc[rr*8+7]);
            }
        }
        __syncthreads();
    }
}

// ---------------- kernel 2: fused 2-layer transformer + head ----------------
extern "C" __global__ void __launch_bounds__(NTHREADS)
main_kernel(const float* __restrict__ feat,
            const int* __restrict__ nbr_idx,
            const int* __restrict__ nbr_valid,   // bool widened to a 4-byte type
            const float* wq1, const float* wo1, const float* bo1,
            const float* w1a, const float* b1a, const float* w1b, const float* b1b,
            const float* g1a, const float* be1a, const float* g1b, const float* be1b,
            const float* wq2, const float* wo2, const float* bo2,
            const float* w2a, const float* b2a, const float* w2b, const float* b2b,
            const float* g2a, const float* be2a, const float* g2b, const float* be2b,
            const float* w4, const float* b4,
            float* __restrict__ out) {
    extern __shared__ char smem_raw[];
    SmemMain* s = (SmemMain*)smem_raw;
    int tid  = threadIdx.x;
    int base = blockIdx.x * BLOCK;

    // load X tile (zero-padded)
    #pragma unroll
    for (int i = tid; i < BLOCK * (DIM / 4); i += NTHREADS) {
        int node = i >> 5;
        int c4   = (i & 31) << 2;
        int g    = base + node;
        float4 v = make_float4(0.f, 0.f, 0.f, 0.f);
        if (g < N_NODES) v = *(const float4*)(feat + (size_t)g * DIM + c4);
        *(float4*)(s->X + node * DIM + c4) = v;
    }
    // neighbor indices + mask flags
    // nbr_valid is a bool array widened by the harness to a 4-byte element
    // (int32 0/1 or float32 0.0/1.0) — in both encodings "valid" <=> nonzero
    // 32-bit word, so an integer != 0 test is dtype-agnostic.
    for (int i = tid; i < BLOCK * KNBR; i += NTHREADS) {
        int node = i / KNBR;
        int j    = i - node * KNBR;
        int g    = base + node;
        int idx = 0, mflag = 1;
        if (g < N_NODES) {
            idx = nbr_idx[(size_t)g * KNBR + j];
            int valid = nbr_valid[(size_t)g * KNBR + j];   // nonzero bits = true
            mflag = (valid == 0) || (g_rowsum[idx] == 0.f);
        }
        s->nidx[i]  = idx;
        s->nmask[i] = mflag;
    }
    __syncthreads();

    run_layer(s, base, wq1, wo1, bo1, w1a, b1a, w1b, b1b,
              g1a, be1a, g1b, be1b, g_Kp1, g_Vp1);
    run_layer(s, base, wq2, wo2, bo2, w2a, b2a, w2b, b2b,
              g2a, be2a, g2b, be2b, g_Kp2, g_Vp2);

    // final: out = tanh(X @ w4 + b4), w4: 128x64
    #pragma unroll
    for (int i = tid; i < DIM * 16; i += NTHREADS) {   // 2048 float4
        int r  = i >> 4;
        int c4 = (i & 15) << 2;
        *(float4*)(s->W + r * 64 + c4) = *(const float4*)(w4 + r * 64 + c4);
    }
    __syncthreads();
    {
        int row = tid >> 3;            // 0..63
        int c0  = (tid & 7) * 8;       // 0..56
        float acc8[8];
        #pragma unroll
        for (int c = 0; c < 8; ++c) acc8[c] = 0.f;
        const float* xp = s->X + row * DIM;
        #pragma unroll 8
        for (int kk = 0; kk < DIM; ++kk) {
            float a = xp[kk];
            float4 w0 = *(const float4*)(s->W + kk * 64 + c0);
            float4 w1 = *(const float4*)(s->W + kk * 64 + c0 + 4);
            acc8[0] = fmaf(a, w0.x, acc8[0]);
            acc8[1] = fmaf(a, w0.y, acc8[1]);
            acc8[2] = fmaf(a, w0.z, acc8[2]);
            acc8[3] = fmaf(a, w0.w, acc8[3]);
            acc8[4] = fmaf(a, w1.x, acc8[4]);
            acc8[5] = fmaf(a, w1.y, acc8[5]);
            acc8[6] = fmaf(a, w1.z, acc8[6]);
            acc8[7] = fmaf(a, w1.w, acc8[7]);
        }
        int g = base + row;
        if (g < N_NODES) {
            #pragma unroll
            for (int c = 0; c < 8; ++c)
                out[(size_t)g * 64 + c0 + c] = tanhf(acc8[c] + b4[c0 + c]);
        }
    }
}

// ---------------- host launch ----------------
extern "C" void kernel_launch(void* const* d_in, const int* in_sizes, int n_in,
                              void* d_out, int out_size) {
    const float* feat    = (const float*)d_in[0];
    const int* nbr_idx   = (const int*)d_in[1];
    const int* nbr_val   = (const int*)d_in[2];
    const float* wq1 = (const float*)d_in[3];
    const float* wk1 = (const float*)d_in[4];
    const float* wv1 = (const float*)d_in[5];
    const float* wo1 = (const float*)d_in[6];
    const float* bo1 = (const float*)d_in[7];
    const float* w1a = (const float*)d_in[8];
    const float* b1a = (const float*)d_in[9];
    const float* w1b = (const float*)d_in[10];
    const float* b1b = (const float*)d_in[11];
    const float* g1a = (const float*)d_in[12];
    const float* be1a = (const float*)d_in[13];
    const float* g1b = (const float*)d_in[14];
    const float* be1b = (const float*)d_in[15];
    const float* wq2 = (const float*)d_in[16];
    const float* wk2 = (const float*)d_in[17];
    const float* wv2 = (const float*)d_in[18];
    const float* wo2 = (const float*)d_in[19];
    const float* bo2 = (const float*)d_in[20];
    const float* w2a = (const float*)d_in[21];
    const float* b2a = (const float*)d_in[22];
    const float* w2b = (const float*)d_in[23];
    const float* b2b = (const float*)d_in[24];
    const float* g2a = (const float*)d_in[25];
    const float* be2a = (const float*)d_in[26];
    const float* g2b = (const float*)d_in[27];
    const float* be2b = (const float*)d_in[28];
    const float* w4 = (const float*)d_in[29];
    const float* b4 = (const float*)d_in[30];
    float* out = (float*)d_out;

    size_t smem_pre  = sizeof(SmemPre);
    size_t smem_main = sizeof(SmemMain);
    cudaFuncSetAttribute(pre_kernel,  cudaFuncAttributeMaxDynamicSharedMemorySize, (int)smem_pre);
    cudaFuncSetAttribute(main_kernel, cudaFuncAttributeMaxDynamicSharedMemorySize, (int)smem_main);

    pre_kernel<<<NTILES, NTHREADS, smem_pre>>>(feat, wk1, wv1, wk2, wv2);
    main_kernel<<<NTILES, NTHREADS, smem_main>>>(
        feat, nbr_idx, nbr_val,
        wq1, wo1, bo1, w1a, b1a, w1b, b1b, g1a, be1a, g1b, be1b,
        wq2, wo2, bo2, w2a, b2a, w2b, b2b, g2a, be2a, g2b, be2b,
        w4, b4, out);
}

// round 5
// speedup vs baseline: 2.0925x; 2.0925x over previous
#include <cuda_runtime.h>

#define N_NODES 300000
#define DIM 128
#define KNBR 5
#define EPS_LN 1e-5f
#define BLOCK 64
#define NTHREADS 512
#define NTILES ((N_NODES + BLOCK - 1) / BLOCK)
#define PAD 68      // stride (floats) of k-major transposed tiles
#define TQS 132     // stride of row-major Q buffer

typedef unsigned long long ull;

// ---------------- global scratch ----------------
__device__ float g_Kp1[(size_t)N_NODES * DIM];
__device__ float g_Vp1[(size_t)N_NODES * DIM];
__device__ float g_Kp2[(size_t)N_NODES * DIM];
__device__ float g_Vp2[(size_t)N_NODES * DIM];
__device__ float g_rowsum[N_NODES];

// ---------------- f32x2 helpers ----------------
__device__ __forceinline__ ull f2x2(float lo, float hi) {
    ull r;
    asm("mov.b64 %0, {%1, %2};" : "=l"(r) : "f"(lo), "f"(hi));
    return r;
}
__device__ __forceinline__ void ffma2(ull& d, ull a, ull b) {
    asm("fma.rn.f32x2 %0, %1, %2, %0;" : "+l"(d) : "l"(a), "l"(b));
}
__device__ __forceinline__ void unpk(ull v, float& lo, float& hi) {
    asm("mov.b64 {%0, %1}, %2;" : "=f"(lo), "=f"(hi) : "l"(v));
}

// ---------------- shared memory layouts ----------------
struct SmemMain {
    float XT[DIM * PAD];        // residual stream, k-major  (8704)
    float UT[DIM * PAD];        // pre-LN gemm output, k-major (8704)
    float W[DIM * DIM];         // weight tile, k-major (row-major of source) (16384)
    float B1[256 * PAD];        // union: HT (256xPAD) | AT (128xPAD) + Tq (64xTQS at +128*PAD)
    int   nidx[BLOCK * KNBR];
    int   nmask[BLOCK * KNBR];
};
struct SmemPre {
    float XT[DIM * PAD];
    float W[DIM * DIM];
};

// ---------------- helpers ----------------
__device__ __forceinline__ void load_w(const float* __restrict__ Wg,
                                       int row0, int col0, int ncols,
                                       float* __restrict__ Ws) {
    int tid = threadIdx.x;
    #pragma unroll
    for (int i = tid; i < DIM * (DIM / 4); i += NTHREADS) {   // 4096 float4
        int r  = i >> 5;
        int c4 = (i & 31) << 2;
        *(float4*)(Ws + r * DIM + c4) =
            *(const float4*)(Wg + (size_t)(row0 + r) * ncols + col0 + c4);
    }
}

__device__ __forceinline__ void zacc(ull acc[8]) {
    #pragma unroll
    for (int i = 0; i < 8; ++i) acc[i] = 0ull;
}

// acc[c*4+rp] accumulates rows (rbase+2rp, rbase+2rp+1), col (cbase+c).
// A: k-major (stride PAD); Ws: k-major (stride DIM).
__device__ __forceinline__ void gemm128(const float* __restrict__ A,
                                        const float* __restrict__ Ws,
                                        int rbase, int ct, ull acc[8]) {
    const float* ap = A + rbase;
    const float* wp = Ws + ct * 2;
    #pragma unroll 4
    for (int k = 0; k < 128; ++k) {
        ulonglong2 a01 = *(const ulonglong2*)(ap);      // rows rbase..+3
        ulonglong2 a23 = *(const ulonglong2*)(ap + 4);  // rows rbase+4..+7
        float2 w2 = *(const float2*)(wp);
        ull w0 = f2x2(w2.x, w2.x);
        ull w1 = f2x2(w2.y, w2.y);
        ffma2(acc[0], a01.x, w0); ffma2(acc[1], a01.y, w0);
        ffma2(acc[2], a23.x, w0); ffma2(acc[3], a23.y, w0);
        ffma2(acc[4], a01.x, w1); ffma2(acc[5], a01.y, w1);
        ffma2(acc[6], a23.x, w1); ffma2(acc[7], a23.y, w1);
        ap += PAD; wp += DIM;
    }
}

// store to transposed (k-major) buffer with bias (+optional relu)
__device__ __forceinline__ void store_t(float* __restrict__ Dst, int dst_col0,
                                        const float* __restrict__ bias,
                                        bool relu, int rbase, int cbase,
                                        const ull acc[8]) {
    #pragma unroll
    for (int c = 0; c < 2; ++c) {
        float bv = bias ? bias[dst_col0 + cbase + c] : 0.f;
        #pragma unroll
        for (int rp = 0; rp < 4; ++rp) {
            float lo, hi;
            unpk(acc[c * 4 + rp], lo, hi);
            lo += bv; hi += bv;
            if (relu) { lo = fmaxf(lo, 0.f); hi = fmaxf(hi, 0.f); }
            *(float2*)(Dst + (size_t)(dst_col0 + cbase + c) * PAD + rbase + rp * 2) =
                make_float2(lo, hi);
        }
    }
}

// LN: XT = LN(XT + UT)*gamma + beta, per row. node = tid>>3, h = tid&7,
// elements e = h + 8*i  (bank-conflict-free for stride PAD=68).
__device__ __forceinline__ void ln_t(float* __restrict__ XT,
                                     const float* __restrict__ UT,
                                     const float* __restrict__ gamma,
                                     const float* __restrict__ beta) {
    int tid  = threadIdx.x;
    int node = tid >> 3;
    int h    = tid & 7;
    float v[16];
    float sum = 0.f;
    #pragma unroll
    for (int i = 0; i < 16; ++i) {
        int e = h + 8 * i;
        v[i] = XT[e * PAD + node] + UT[e * PAD + node];
        sum += v[i];
    }
    sum += __shfl_xor_sync(0xffffffffu, sum, 1);
    sum += __shfl_xor_sync(0xffffffffu, sum, 2);
    sum += __shfl_xor_sync(0xffffffffu, sum, 4);
    float m = sum * (1.f / 128.f);
    float sq = 0.f;
    #pragma unroll
    for (int i = 0; i < 16; ++i) { float d = v[i] - m; sq = fmaf(d, d, sq); }
    sq += __shfl_xor_sync(0xffffffffu, sq, 1);
    sq += __shfl_xor_sync(0xffffffffu, sq, 2);
    sq += __shfl_xor_sync(0xffffffffu, sq, 4);
    float inv = rsqrtf(sq * (1.f / 128.f) + EPS_LN);
    #pragma unroll
    for (int i = 0; i < 16; ++i) {
        int e = h + 8 * i;
        XT[e * PAD + node] = (v[i] - m) * inv * gamma[e] + beta[e];
    }
}

// ---------------- one transformer layer ----------------
__device__ void run_layer(SmemMain* s, int base,
                          const float* wq, const float* wo, const float* bo,
                          const float* wa, const float* ba,
                          const float* wb, const float* bb,
                          const float* ga, const float* bea,
                          const float* gb, const float* beb,
                          const float* __restrict__ Kp,
                          const float* __restrict__ Vp) {
    int tid  = threadIdx.x;
    int lane = tid & 31, warp = tid >> 5;
    int rgrp = (warp & 3) * 2 + (lane >> 4);     // 0..7
    int ct   = (warp >> 2) * 16 + (lane & 15);   // 0..63
    int rbase = rgrp * 8, cbase = ct * 2;
    float* AT = s->B1;                 // 128 x PAD
    float* Tq = s->B1 + 128 * PAD;     // 64 x TQS
    float* HT = s->B1;                 // 256 x PAD (after attention phase)
    ull acc[8];

    // ---- 1. Q = X @ wq -> Tq (row-major, no bias) ----
    load_w(wq, 0, 0, DIM, s->W);
    __syncthreads();
    zacc(acc);
    gemm128(s->XT, s->W, rbase, ct, acc);
    #pragma unroll
    for (int c = 0; c < 2; ++c)
        #pragma unroll
        for (int rp = 0; rp < 4; ++rp) {
            float lo, hi;
            unpk(acc[c * 4 + rp], lo, hi);
            Tq[(rbase + rp * 2)     * TQS + cbase + c] = lo;
            Tq[(rbase + rp * 2 + 1) * TQS + cbase + c] = hi;
        }
    __syncthreads();

    // ---- 2. attention (writes AT, k-major); preload wo concurrently ----
    load_w(wo, 0, 0, DIM, s->W);
    {
        int node = tid >> 3;
        int h    = tid & 7;
        int g    = base + node;
        if (g < N_NODES) {
            const float* qs = Tq + node * TQS + h * 16;
            float q[16];
            #pragma unroll
            for (int t = 0; t < 4; ++t) {
                float4 q4 = *(const float4*)(qs + t * 4);
                q[4*t] = q4.x; q[4*t+1] = q4.y; q[4*t+2] = q4.z; q[4*t+3] = q4.w;
            }
            float dots[KNBR]; bool msk[KNBR];
            #pragma unroll
            for (int j = 0; j < KNBR; ++j) {
                int mflag = s->nmask[node * KNBR + j];
                msk[j] = (mflag != 0);
                if (mflag) { dots[j] = -1e30f; continue; }
                int idx = s->nidx[node * KNBR + j];
                const float4* kp = (const float4*)(Kp + (size_t)idx * DIM + h * 16);
                float d = 0.f;
                #pragma unroll
                for (int t = 0; t < 4; ++t) {
                    float4 k4 = kp[t];
                    d = fmaf(q[4*t+0], k4.x, d);
                    d = fmaf(q[4*t+1], k4.y, d);
                    d = fmaf(q[4*t+2], k4.z, d);
                    d = fmaf(q[4*t+3], k4.w, d);
                }
                dots[j] = d * 0.25f;
            }
            float mmax = -1e30f;
            #pragma unroll
            for (int j = 0; j < KNBR; ++j) mmax = fmaxf(mmax, dots[j]);
            float e[KNBR]; float ssum = 0.f;
            #pragma unroll
            for (int j = 0; j < KNBR; ++j) {
                e[j] = msk[j] ? 0.f : __expf(dots[j] - mmax);
                ssum += e[j];
            }
            float inv = 1.f / ssum;
            float4 o[4];
            #pragma unroll
            for (int t = 0; t < 4; ++t) o[t] = make_float4(0.f, 0.f, 0.f, 0.f);
            #pragma unroll
            for (int j = 0; j < KNBR; ++j) {
                if (!msk[j]) {
                    int idx = s->nidx[node * KNBR + j];
                    const float4* vp = (const float4*)(Vp + (size_t)idx * DIM + h * 16);
                    float a = e[j] * inv;
                    #pragma unroll
                    for (int t = 0; t < 4; ++t) {
                        float4 v4 = vp[t];
                        o[t].x = fmaf(a, v4.x, o[t].x);
                        o[t].y = fmaf(a, v4.y, o[t].y);
                        o[t].z = fmaf(a, v4.z, o[t].z);
                        o[t].w = fmaf(a, v4.w, o[t].w);
                    }
                }
            }
            // write transposed: AT[c][node]
            #pragma unroll
            for (int t = 0; t < 4; ++t) {
                int cc = h * 16 + t * 4;
                AT[(cc + 0) * PAD + node] = o[t].x;
                AT[(cc + 1) * PAD + node] = o[t].y;
                AT[(cc + 2) * PAD + node] = o[t].z;
                AT[(cc + 3) * PAD + node] = o[t].w;
            }
        }
    }
    __syncthreads();

    // ---- 3. U = attn @ wo + bo -> UT ----
    zacc(acc);
    gemm128(AT, s->W, rbase, ct, acc);
    store_t(s->UT, 0, bo, false, rbase, cbase, acc);
    __syncthreads();

    // ---- 4. X = LN(X + U) ----
    ln_t(s->XT, s->UT, ga, bea);
    __syncthreads();

    // ---- 5. H = relu(X @ wa + ba) -> HT (256 x PAD, k-major), two col halves ----
    #pragma unroll
    for (int half = 0; half < 2; ++half) {
        load_w(wa, 0, half * 128, 256, s->W);
        __syncthreads();
        zacc(acc);
        gemm128(s->XT, s->W, rbase, ct, acc);
        store_t(HT, half * 128, ba, true, rbase, cbase, acc);
        __syncthreads();
    }

    // ---- 6. F = H @ wb + bb -> UT, two K halves ----
    zacc(acc);
    load_w(wb, 0, 0, DIM, s->W);
    __syncthreads();
    gemm128(HT, s->W, rbase, ct, acc);
    __syncthreads();
    load_w(wb, 128, 0, DIM, s->W);
    __syncthreads();
    gemm128(HT + 128 * PAD, s->W, rbase, ct, acc);
    store_t(s->UT, 0, bb, false, rbase, cbase, acc);
    __syncthreads();

    // ---- 7. X = LN(X + F) ----
    ln_t(s->XT, s->UT, gb, beb);
    __syncthreads();
}

// ---------------- kernel 1: Kp/Vp projections + row sums ----------------
extern "C" __global__ void __launch_bounds__(NTHREADS)
pre_kernel(const float* __restrict__ feat,
           const float* __restrict__ wk1, const float* __restrict__ wv1,
           const float* __restrict__ wk2, const float* __restrict__ wv2) {
    extern __shared__ char smem_raw[];
    SmemPre* s = (SmemPre*)smem_raw;
    int tid  = threadIdx.x;
    int base = blockIdx.x * BLOCK;

    // load X tile transposed (zero-padded)
    #pragma unroll
    for (int i = tid; i < BLOCK * 32; i += NTHREADS) {
        int node = i >> 5;
        int k4   = (i & 31) << 2;
        int g    = base + node;
        float4 v = make_float4(0.f, 0.f, 0.f, 0.f);
        if (g < N_NODES) v = *(const float4*)(feat + (size_t)g * DIM + k4);
        s->XT[(k4 + 0) * PAD + node] = v.x;
        s->XT[(k4 + 1) * PAD + node] = v.y;
        s->XT[(k4 + 2) * PAD + node] = v.z;
        s->XT[(k4 + 3) * PAD + node] = v.w;
    }
    __syncthreads();

    // row sums
    {
        int node = tid >> 3;
        int h    = tid & 7;
        float ssum = 0.f;
        #pragma unroll
        for (int i = 0; i < 16; ++i) ssum += s->XT[(h + 8 * i) * PAD + node];
        ssum += __shfl_xor_sync(0xffffffffu, ssum, 1);
        ssum += __shfl_xor_sync(0xffffffffu, ssum, 2);
        ssum += __shfl_xor_sync(0xffffffffu, ssum, 4);
        int g = base + node;
        if (h == 0 && g < N_NODES) g_rowsum[g] = ssum;
    }

    int lane = tid & 31, warp = tid >> 5;
    int rgrp = (warp & 3) * 2 + (lane >> 4);
    int ct   = (warp >> 2) * 16 + (lane & 15);
    int rbase = rgrp * 8, cbase = ct * 2;
    const float* ws_in[4] = {wk1, wv1, wk2, wv2};
    float* outs[4] = {g_Kp1, g_Vp1, g_Kp2, g_Vp2};
    ull acc[8];
    #pragma unroll
    for (int w = 0; w < 4; ++w) {
        load_w(ws_in[w], 0, 0, DIM, s->W);
        __syncthreads();
        zacc(acc);
        gemm128(s->XT, s->W, rbase, ct, acc);
        #pragma unroll
        for (int c = 0; c < 2; ++c)
            #pragma unroll
            for (int rp = 0; rp < 4; ++rp) {
                float lo, hi;
                unpk(acc[c * 4 + rp], lo, hi);
                int g0 = base + rbase + rp * 2;
                if (g0 < N_NODES)     outs[w][(size_t)g0 * DIM + cbase + c]       = lo;
                if (g0 + 1 < N_NODES) outs[w][(size_t)(g0 + 1) * DIM + cbase + c] = hi;
            }
        __syncthreads();
    }
}

// ---------------- kernel 2: fused 2-layer transformer + head ----------------
extern "C" __global__ void __launch_bounds__(NTHREADS)
main_kernel(const float* __restrict__ feat,
            const int* __restrict__ nbr_idx,
            const int* __restrict__ nbr_valid,
            const float* wq1, const float* wo1, const float* bo1,
            const float* w1a, const float* b1a, const float* w1b, const float* b1b,
            const float* g1a, const float* be1a, const float* g1b, const float* be1b,
            const float* wq2, const float* wo2, const float* bo2,
            const float* w2a, const float* b2a, const float* w2b, const float* b2b,
            const float* g2a, const float* be2a, const float* g2b, const float* be2b,
            const float* w4, const float* b4,
            float* __restrict__ out) {
    extern __shared__ char smem_raw[];
    SmemMain* s = (SmemMain*)smem_raw;
    int tid  = threadIdx.x;
    int base = blockIdx.x * BLOCK;

    // load X tile transposed (zero-padded)
    #pragma unroll
    for (int i = tid; i < BLOCK * 32; i += NTHREADS) {
        int node = i >> 5;
        int k4   = (i & 31) << 2;
        int g    = base + node;
        float4 v = make_float4(0.f, 0.f, 0.f, 0.f);
        if (g < N_NODES) v = *(const float4*)(feat + (size_t)g * DIM + k4);
        s->XT[(k4 + 0) * PAD + node] = v.x;
        s->XT[(k4 + 1) * PAD + node] = v.y;
        s->XT[(k4 + 2) * PAD + node] = v.z;
        s->XT[(k4 + 3) * PAD + node] = v.w;
    }
    // neighbor indices + mask flags (nbr_valid: bool widened to 4-byte; nonzero = true)
    for (int i = tid; i < BLOCK * KNBR; i += NTHREADS) {
        int node = i / KNBR;
        int j    = i - node * KNBR;
        int g    = base + node;
        int idx = 0, mflag = 1;
        if (g < N_NODES) {
            idx = nbr_idx[(size_t)g * KNBR + j];
            int valid = nbr_valid[(size_t)g * KNBR + j];
            mflag = (valid == 0) || (g_rowsum[idx] == 0.f);
        }
        s->nidx[i]  = idx;
        s->nmask[i] = mflag;
    }
    __syncthreads();

    run_layer(s, base, wq1, wo1, bo1, w1a, b1a, w1b, b1b,
              g1a, be1a, g1b, be1b, g_Kp1, g_Vp1);
    run_layer(s, base, wq2, wo2, bo2, w2a, b2a, w2b, b2b,
              g2a, be2a, g2b, be2b, g_Kp2, g_Vp2);

    // final: out = tanh(X @ w4 + b4), w4: 128x64
    #pragma unroll
    for (int i = tid; i < DIM * 16; i += NTHREADS) {   // 2048 float4
        int r  = i >> 4;
        int c4 = (i & 15) << 2;
        *(float4*)(s->W + r * 64 + c4) = *(const float4*)(w4 + r * 64 + c4);
    }
    __syncthreads();
    {
        int node = tid >> 3;
        int c0   = (tid & 7) * 8;
        float acc8[8];
        #pragma unroll
        for (int c = 0; c < 8; ++c) acc8[c] = 0.f;
        #pragma unroll 4
        for (int kk = 0; kk < DIM; ++kk) {
            float a = s->XT[kk * PAD + node];
            float4 w0 = *(const float4*)(s->W + kk * 64 + c0);
            float4 w1 = *(const float4*)(s->W + kk * 64 + c0 + 4);
            acc8[0] = fmaf(a, w0.x, acc8[0]);
            acc8[1] = fmaf(a, w0.y, acc8[1]);
            acc8[2] = fmaf(a, w0.z, acc8[2]);
            acc8[3] = fmaf(a, w0.w, acc8[3]);
            acc8[4] = fmaf(a, w1.x, acc8[4]);
            acc8[5] = fmaf(a, w1.y, acc8[5]);
            acc8[6] = fmaf(a, w1.z, acc8[6]);
            acc8[7] = fmaf(a, w1.w, acc8[7]);
        }
        int g = base + node;
        if (g < N_NODES) {
            #pragma unroll
            for (int c = 0; c < 8; ++c)
                out[(size_t)g * 64 + c0 + c] = tanhf(acc8[c] + b4[c0 + c]);
        }
    }
}

// ---------------- host launch ----------------
extern "C" void kernel_launch(void* const* d_in, const int* in_sizes, int n_in,
                              void* d_out, int out_size) {
    const float* feat  = (const float*)d_in[0];
    const int* nbr_idx = (const int*)d_in[1];
    const int* nbr_val = (const int*)d_in[2];
    const float* wq1 = (const float*)d_in[3];
    const float* wk1 = (const float*)d_in[4];
    const float* wv1 = (const float*)d_in[5];
    const float* wo1 = (const float*)d_in[6];
    const float* bo1 = (const float*)d_in[7];
    const float* w1a = (const float*)d_in[8];
    const float* b1a = (const float*)d_in[9];
    const float* w1b = (const float*)d_in[10];
    const float* b1b = (const float*)d_in[11];
    const float* g1a = (const float*)d_in[12];
    const float* be1a = (const float*)d_in[13];
    const float* g1b = (const float*)d_in[14];
    const float* be1b = (const float*)d_in[15];
    const float* wq2 = (const float*)d_in[16];
    const float* wk2 = (const float*)d_in[17];
    const float* wv2 = (const float*)d_in[18];
    const float* wo2 = (const float*)d_in[19];
    const float* bo2 = (const float*)d_in[20];
    const float* w2a = (const float*)d_in[21];
    const float* b2a = (const float*)d_in[22];
    const float* w2b = (const float*)d_in[23];
    const float* b2b = (const float*)d_in[24];
    const float* g2a = (const float*)d_in[25];
    const float* be2a = (const float*)d_in[26];
    const float* g2b = (const float*)d_in[27];
    const float* be2b = (const float*)d_in[28];
    const float* w4 = (const float*)d_in[29];
    const float* b4 = (const float*)d_in[30];
    float* out = (float*)d_out;

    size_t smem_pre  = sizeof(SmemPre);
    size_t smem_main = sizeof(SmemMain);
    cudaFuncSetAttribute(pre_kernel,  cudaFuncAttributeMaxDynamicSharedMemorySize, (int)smem_pre);
    cudaFuncSetAttribute(main_kernel, cudaFuncAttributeMaxDynamicSharedMemorySize, (int)smem_main);

    pre_kernel<<<NTILES, NTHREADS, smem_pre>>>(feat, wk1, wv1, wk2, wv2);
    main_kernel<<<NTILES, NTHREADS, smem_main>>>(
        feat, nbr_idx, nbr_val,
        wq1, wo1, bo1, w1a, b1a, w1b, b1b, g1a, be1a, g1b, be1b,
        wq2, wo2, bo2, w2a, b2a, w2b, b2b, g2a, be2a, g2b, be2b,
        w4, b4, out);
}

// round 7
// speedup vs baseline: 2.3030x; 1.1006x over previous
#include <cuda_runtime.h>

#define N_NODES 300000
#define DIM 128
#define KNBR 5
#define EPS_LN 1e-5f
#define BLOCK 64
#define NTHREADS 512
#define NTILES ((N_NODES + BLOCK - 1) / BLOCK)
#define PAD 68      // stride (floats) of k-major transposed tiles
#define TQS 132     // stride of row-major Q buffer

typedef unsigned long long ull;

// ---------------- global scratch ----------------
__device__ float g_Kp1[(size_t)N_NODES * DIM];
__device__ float g_Vp1[(size_t)N_NODES * DIM];
__device__ float g_Kp2[(size_t)N_NODES * DIM];
__device__ float g_Vp2[(size_t)N_NODES * DIM];
__device__ float g_rowsum[N_NODES];

// ---------------- f32x2 helpers ----------------
__device__ __forceinline__ ull f2x2(float lo, float hi) {
    ull r;
    asm("mov.b64 %0, {%1, %2};" : "=l"(r) : "f"(lo), "f"(hi));
    return r;
}
__device__ __forceinline__ void ffma2(ull& d, ull a, ull b) {
    asm("fma.rn.f32x2 %0, %1, %2, %0;" : "+l"(d) : "l"(a), "l"(b));
}
__device__ __forceinline__ void unpk(ull v, float& lo, float& hi) {
    asm("mov.b64 {%0, %1}, %2;" : "=f"(lo), "=f"(hi) : "l"(v));
}
__device__ __forceinline__ unsigned sptr(const void* p) {
    return (unsigned)__cvta_generic_to_shared(p);
}
__device__ __forceinline__ void cp16(unsigned saddr, const void* g) {
    asm volatile("cp.async.cg.shared.global [%0], [%1], 16;" :: "r"(saddr), "l"(g));
}
__device__ __forceinline__ void cp_wait() {
    asm volatile("cp.async.commit_group;\n\tcp.async.wait_group 0;" ::: "memory");
}

// ---------------- shared memory layouts ----------------
struct SmemMain {
    float XT[DIM * PAD];   // residual stream, k-major          (34816 B)
    float W[64 * DIM];     // current 64x128 weight k-chunk     (32768 B)
    float S[DIM * PAD];    // scratch: Tq | AT | U | H | F      (34816 B)
    int   nidx[BLOCK * KNBR];
    int   nmask[BLOCK * KNBR];
};                          // ~102.5 KB -> 2 CTAs/SM
struct SmemPre {
    float XT[DIM * PAD];
    float W[64 * DIM];
};                          // ~66 KB

// ---------------- W chunk loaders (cp.async) ----------------
// issue loads for a 64-row x 128-col chunk of Wg (row-major, row stride ncols)
__device__ __forceinline__ void issue_chunk(const float* __restrict__ Wg,
                                            int row0, int col0, int ncols,
                                            float* __restrict__ Ws) {
    int tid = threadIdx.x;
    #pragma unroll
    for (int i = tid; i < 2048; i += NTHREADS) {   // 2048 float4
        int r  = i >> 5;
        int c4 = (i & 31) << 2;
        cp16(sptr(Ws + r * DIM + c4),
             Wg + (size_t)(row0 + r) * ncols + col0 + c4);
    }
}
// full staged load: barrier (drain prior W readers), load, barrier
__device__ __forceinline__ void stage_chunk(const float* __restrict__ Wg,
                                            int row0, int col0, int ncols,
                                            float* __restrict__ Ws) {
    __syncthreads();
    issue_chunk(Wg, row0, col0, ncols, Ws);
    cp_wait();
    __syncthreads();
}

__device__ __forceinline__ void zacc(ull acc[8]) {
    #pragma unroll
    for (int i = 0; i < 8; ++i) acc[i] = 0ull;
}

// acc[c*4+rp] += rows (rbase+2rp, +1), col (ct*2+c); A k-major stride PAD, Ws stride DIM, K=64
__device__ __forceinline__ void gemm64(const float* __restrict__ A,
                                       const float* __restrict__ Ws,
                                       int rbase, int ct, ull acc[8]) {
    const float* ap = A + rbase;
    const float* wp = Ws + ct * 2;
    #pragma unroll 8
    for (int k = 0; k < 64; ++k) {
        ulonglong2 a01 = *(const ulonglong2*)(ap);
        ulonglong2 a23 = *(const ulonglong2*)(ap + 4);
        float2 w2 = *(const float2*)(wp);
        ull w0 = f2x2(w2.x, w2.x);
        ull w1 = f2x2(w2.y, w2.y);
        ffma2(acc[0], a01.x, w0); ffma2(acc[1], a01.y, w0);
        ffma2(acc[2], a23.x, w0); ffma2(acc[3], a23.y, w0);
        ffma2(acc[4], a01.x, w1); ffma2(acc[5], a01.y, w1);
        ffma2(acc[6], a23.x, w1); ffma2(acc[7], a23.y, w1);
        ap += PAD; wp += DIM;
    }
}

// store acc to k-major buffer with bias (+optional relu)
__device__ __forceinline__ void store_t(float* __restrict__ Dst,
                                        const float* __restrict__ bias,
                                        bool relu, int rbase, int cbase,
                                        const ull acc[8]) {
    #pragma unroll
    for (int c = 0; c < 2; ++c) {
        float bv = bias[cbase + c];
        #pragma unroll
        for (int rp = 0; rp < 4; ++rp) {
            float lo, hi;
            unpk(acc[c * 4 + rp], lo, hi);
            lo += bv; hi += bv;
            if (relu) { lo = fmaxf(lo, 0.f); hi = fmaxf(hi, 0.f); }
            *(float2*)(Dst + (size_t)(cbase + c) * PAD + rbase + rp * 2) =
                make_float2(lo, hi);
        }
    }
}

// LN: XT = LN(XT + UT)*gamma + beta. node = tid>>3, h = tid&7, e = h + 8*i.
__device__ __forceinline__ void ln_t(float* __restrict__ XT,
                                     const float* __restrict__ UT,
                                     const float* __restrict__ gamma,
                                     const float* __restrict__ beta) {
    int tid  = threadIdx.x;
    int node = tid >> 3;
    int h    = tid & 7;
    float v[16];
    float sum = 0.f;
    #pragma unroll
    for (int i = 0; i < 16; ++i) {
        int e = h + 8 * i;
        v[i] = XT[e * PAD + node] + UT[e * PAD + node];
        sum += v[i];
    }
    sum += __shfl_xor_sync(0xffffffffu, sum, 1);
    sum += __shfl_xor_sync(0xffffffffu, sum, 2);
    sum += __shfl_xor_sync(0xffffffffu, sum, 4);
    float m = sum * (1.f / 128.f);
    float sq = 0.f;
    #pragma unroll
    for (int i = 0; i < 16; ++i) { float d = v[i] - m; sq = fmaf(d, d, sq); }
    sq += __shfl_xor_sync(0xffffffffu, sq, 1);
    sq += __shfl_xor_sync(0xffffffffu, sq, 2);
    sq += __shfl_xor_sync(0xffffffffu, sq, 4);
    float inv = rsqrtf(sq * (1.f / 128.f) + EPS_LN);
    #pragma unroll
    for (int i = 0; i < 16; ++i) {
        int e = h + 8 * i;
        XT[e * PAD + node] = (v[i] - m) * inv * gamma[e] + beta[e];
    }
}

// ---------------- one transformer layer ----------------
__device__ void run_layer(SmemMain* s, int base,
                          const float* wq, const float* wo, const float* bo,
                          const float* wa, const float* ba,
                          const float* wb, const float* bb,
                          const float* ga, const float* bea,
                          const float* gb, const float* beb,
                          const float* __restrict__ Kp,
                          const float* __restrict__ Vp) {
    int tid  = threadIdx.x;
    int lane = tid & 31, warp = tid >> 5;
    int rgrp = (warp & 3) * 2 + (lane >> 4);     // 0..7
    int ct   = (warp >> 2) * 16 + (lane & 15);   // 0..63
    int rbase = rgrp * 8, cbase = ct * 2;
    float* Tq = s->S;          // row-major 64 x TQS (8448 <= 8704 floats)
    ull acc[8];

    // ---- 1. Q = X @ wq (two k-halves) -> Tq ----
    zacc(acc);
    stage_chunk(wq, 0, 0, DIM, s->W);
    gemm64(s->XT, s->W, rbase, ct, acc);
    stage_chunk(wq, 64, 0, DIM, s->W);
    gemm64(s->XT + 64 * PAD, s->W, rbase, ct, acc);
    #pragma unroll
    for (int c = 0; c < 2; ++c)
        #pragma unroll
        for (int rp = 0; rp < 4; ++rp) {
            float lo, hi;
            unpk(acc[c * 4 + rp], lo, hi);
            Tq[(rbase + rp * 2)     * TQS + cbase + c] = lo;
            Tq[(rbase + rp * 2 + 1) * TQS + cbase + c] = hi;
        }
    __syncthreads();   // Tq visible; W readers (Q gemm) done

    // prefetch wo chunk 0 while attention gathers run
    issue_chunk(wo, 0, 0, DIM, s->W);

    // ---- 2. attention; result overwrites Tq region as k-major AT ----
    float4 o[4];
    #pragma unroll
    for (int t = 0; t < 4; ++t) o[t] = make_float4(0.f, 0.f, 0.f, 0.f);
    {
        int node = tid >> 3;
        int h    = tid & 7;
        int g    = base + node;
        if (g < N_NODES) {
            const float* qs = Tq + node * TQS + h * 16;
            float q[16];
            #pragma unroll
            for (int t = 0; t < 4; ++t) {
                float4 q4 = *(const float4*)(qs + t * 4);
                q[4*t] = q4.x; q[4*t+1] = q4.y; q[4*t+2] = q4.z; q[4*t+3] = q4.w;
            }
            float dots[KNBR]; bool msk[KNBR];
            #pragma unroll
            for (int j = 0; j < KNBR; ++j) {
                int mflag = s->nmask[node * KNBR + j];
                msk[j] = (mflag != 0);
                if (mflag) { dots[j] = -1e30f; continue; }
                int idx = s->nidx[node * KNBR + j];
                const float4* kp = (const float4*)(Kp + (size_t)idx * DIM + h * 16);
                float d = 0.f;
                #pragma unroll
                for (int t = 0; t < 4; ++t) {
                    float4 k4 = kp[t];
                    d = fmaf(q[4*t+0], k4.x, d);
                    d = fmaf(q[4*t+1], k4.y, d);
                    d = fmaf(q[4*t+2], k4.z, d);
                    d = fmaf(q[4*t+3], k4.w, d);
                }
                dots[j] = d * 0.25f;
            }
            float mmax = -1e30f;
            #pragma unroll
            for (int j = 0; j < KNBR; ++j) mmax = fmaxf(mmax, dots[j]);
            float e[KNBR]; float ssum = 0.f;
            #pragma unroll
            for (int j = 0; j < KNBR; ++j) {
                e[j] = msk[j] ? 0.f : __expf(dots[j] - mmax);
                ssum += e[j];
            }
            float inv = 1.f / ssum;
            #pragma unroll
            for (int j = 0; j < KNBR; ++j) {
                if (!msk[j]) {
                    int idx = s->nidx[node * KNBR + j];
                    const float4* vp = (const float4*)(Vp + (size_t)idx * DIM + h * 16);
                    float a = e[j] * inv;
                    #pragma unroll
                    for (int t = 0; t < 4; ++t) {
                        float4 v4 = vp[t];
                        o[t].x = fmaf(a, v4.x, o[t].x);
                        o[t].y = fmaf(a, v4.y, o[t].y);
                        o[t].z = fmaf(a, v4.z, o[t].z);
                        o[t].w = fmaf(a, v4.w, o[t].w);
                    }
                }
            }
        }
    }
    __syncthreads();   // everyone finished reading Tq
    {
        int node = tid >> 3;
        int h    = tid & 7;
        #pragma unroll
        for (int t = 0; t < 4; ++t) {
            int cc = h * 16 + t * 4;
            s->S[(cc + 0) * PAD + node] = o[t].x;
            s->S[(cc + 1) * PAD + node] = o[t].y;
            s->S[(cc + 2) * PAD + node] = o[t].z;
            s->S[(cc + 3) * PAD + node] = o[t].w;
        }
    }
    cp_wait();
    __syncthreads();   // AT + wo chunk0 ready

    // ---- 3. U = attn @ wo + bo ----
    zacc(acc);
    gemm64(s->S, s->W, rbase, ct, acc);
    stage_chunk(wo, 64, 0, DIM, s->W);
    gemm64(s->S + 64 * PAD, s->W, rbase, ct, acc);
    __syncthreads();                 // all done reading AT
    store_t(s->S, bo, false, rbase, cbase, acc);   // U over AT
    __syncthreads();

    // ---- 4. X = LN(X + U) ----
    ln_t(s->XT, s->S, ga, bea);
    __syncthreads();

    // ---- 5/6. FFN: per output-half, H-half -> accF ----
    ull accF[8]; zacc(accF);
    #pragma unroll
    for (int h = 0; h < 2; ++h) {
        zacc(acc);
        stage_chunk(wa, 0, h * 128, 256, s->W);
        gemm64(s->XT, s->W, rbase, ct, acc);
        stage_chunk(wa, 64, h * 128, 256, s->W);
        gemm64(s->XT + 64 * PAD, s->W, rbase, ct, acc);
        __syncthreads();            // prior S readers done
        store_t(s->S, ba + h * 128, true, rbase, cbase, acc);  // H-half
        __syncthreads();
        stage_chunk(wb, h * 128, 0, DIM, s->W);
        gemm64(s->S, s->W, rbase, ct, accF);
        stage_chunk(wb, h * 128 + 64, 0, DIM, s->W);
        gemm64(s->S + 64 * PAD, s->W, rbase, ct, accF);
    }
    __syncthreads();                // all done reading H
    store_t(s->S, bb, false, rbase, cbase, accF);   // F
    __syncthreads();

    // ---- 7. X = LN(X + F) ----
    ln_t(s->XT, s->S, gb, beb);
    __syncthreads();
}

// ---------------- kernel 1: Kp/Vp projections + row sums ----------------
extern "C" __global__ void __launch_bounds__(NTHREADS, 2)
pre_kernel(const float* __restrict__ feat,
           const float* __restrict__ wk1, const float* __restrict__ wv1,
           const float* __restrict__ wk2, const float* __restrict__ wv2) {
    extern __shared__ char smem_raw[];
    SmemPre* s = (SmemPre*)smem_raw;
    int tid  = threadIdx.x;
    int base = blockIdx.x * BLOCK;

    #pragma unroll
    for (int i = tid; i < BLOCK * 32; i += NTHREADS) {
        int node = i >> 5;
        int k4   = (i & 31) << 2;
        int g    = base + node;
        float4 v = make_float4(0.f, 0.f, 0.f, 0.f);
        if (g < N_NODES) v = *(const float4*)(feat + (size_t)g * DIM + k4);
        s->XT[(k4 + 0) * PAD + node] = v.x;
        s->XT[(k4 + 1) * PAD + node] = v.y;
        s->XT[(k4 + 2) * PAD + node] = v.z;
        s->XT[(k4 + 3) * PAD + node] = v.w;
    }
    __syncthreads();

    {   // row sums
        int node = tid >> 3;
        int h    = tid & 7;
        float ssum = 0.f;
        #pragma unroll
        for (int i = 0; i < 16; ++i) ssum += s->XT[(h + 8 * i) * PAD + node];
        ssum += __shfl_xor_sync(0xffffffffu, ssum, 1);
        ssum += __shfl_xor_sync(0xffffffffu, ssum, 2);
        ssum += __shfl_xor_sync(0xffffffffu, ssum, 4);
        int g = base + node;
        if (h == 0 && g < N_NODES) g_rowsum[g] = ssum;
    }

    int lane = tid & 31, warp = tid >> 5;
    int rgrp = (warp & 3) * 2 + (lane >> 4);
    int ct   = (warp >> 2) * 16 + (lane & 15);
    int rbase = rgrp * 8, cbase = ct * 2;
    const float* ws_in[4] = {wk1, wv1, wk2, wv2};
    float* outs[4] = {g_Kp1, g_Vp1, g_Kp2, g_Vp2};
    ull acc[8];
    #pragma unroll
    for (int w = 0; w < 4; ++w) {
        zacc(acc);
        stage_chunk(ws_in[w], 0, 0, DIM, s->W);
        gemm64(s->XT, s->W, rbase, ct, acc);
        stage_chunk(ws_in[w], 64, 0, DIM, s->W);
        gemm64(s->XT + 64 * PAD, s->W, rbase, ct, acc);
        #pragma unroll
        for (int c = 0; c < 2; ++c)
            #pragma unroll
            for (int rp = 0; rp < 4; ++rp) {
                float lo, hi;
                unpk(acc[c * 4 + rp], lo, hi);
                int g0 = base + rbase + rp * 2;
                if (g0 < N_NODES)     outs[w][(size_t)g0 * DIM + cbase + c]       = lo;
                if (g0 + 1 < N_NODES) outs[w][(size_t)(g0 + 1) * DIM + cbase + c] = hi;
            }
    }
}

// ---------------- kernel 2: fused 2-layer transformer + head ----------------
extern "C" __global__ void __launch_bounds__(NTHREADS, 2)
main_kernel(const float* __restrict__ feat,
            const int* __restrict__ nbr_idx,
            const int* __restrict__ nbr_valid,
            const float* wq1, const float* wo1, const float* bo1,
            const float* w1a, const float* b1a, const float* w1b, const float* b1b,
            const float* g1a, const float* be1a, const float* g1b, const float* be1b,
            const float* wq2, const float* wo2, const float* bo2,
            const float* w2a, const float* b2a, const float* w2b, const float* b2b,
            const float* g2a, const float* be2a, const float* g2b, const float* be2b,
            const float* w4, const float* b4,
            float* __restrict__ out) {
    extern __shared__ char smem_raw[];
    SmemMain* s = (SmemMain*)smem_raw;
    int tid  = threadIdx.x;
    int base = blockIdx.x * BLOCK;

    #pragma unroll
    for (int i = tid; i < BLOCK * 32; i += NTHREADS) {
        int node = i >> 5;
        int k4   = (i & 31) << 2;
        int g    = base + node;
        float4 v = make_float4(0.f, 0.f, 0.f, 0.f);
        if (g < N_NODES) v = *(const float4*)(feat + (size_t)g * DIM + k4);
        s->XT[(k4 + 0) * PAD + node] = v.x;
        s->XT[(k4 + 1) * PAD + node] = v.y;
        s->XT[(k4 + 2) * PAD + node] = v.z;
        s->XT[(k4 + 3) * PAD + node] = v.w;
    }
    for (int i = tid; i < BLOCK * KNBR; i += NTHREADS) {
        int node = i / KNBR;
        int j    = i - node * KNBR;
        int g    = base + node;
        int idx = 0, mflag = 1;
        if (g < N_NODES) {
            idx = nbr_idx[(size_t)g * KNBR + j];
            int valid = nbr_valid[(size_t)g * KNBR + j];   // nonzero = true
            mflag = (valid == 0) || (g_rowsum[idx] == 0.f);
        }
        s->nidx[i]  = idx;
        s->nmask[i] = mflag;
    }
    __syncthreads();

    run_layer(s, base, wq1, wo1, bo1, w1a, b1a, w1b, b1b,
              g1a, be1a, g1b, be1b, g_Kp1, g_Vp1);
    run_layer(s, base, wq2, wo2, bo2, w2a, b2a, w2b, b2b,
              g2a, be2a, g2b, be2b, g_Kp2, g_Vp2);

    // ---- head: out = tanh(X @ w4 + b4), w4: 128x64 ----
    __syncthreads();
    {
        #pragma unroll
        for (int i = tid; i < 2048; i += NTHREADS) {   // 2048 float4
            int r  = i >> 4;
            int c4 = (i & 15) << 2;
            cp16(sptr(s->W + r * 64 + c4), w4 + r * 64 + c4);
        }
        cp_wait();
    }
    __syncthreads();
    {
        int node = tid >> 3;
        int c0   = (tid & 7) * 8;
        float acc8[8];
        #pragma unroll
        for (int c = 0; c < 8; ++c) acc8[c] = 0.f;
        #pragma unroll 4
        for (int kk = 0; kk < DIM; ++kk) {
            float a = s->XT[kk * PAD + node];
            float4 w0 = *(const float4*)(s->W + kk * 64 + c0);
            float4 w1 = *(const float4*)(s->W + kk * 64 + c0 + 4);
            acc8[0] = fmaf(a, w0.x, acc8[0]);
            acc8[1] = fmaf(a, w0.y, acc8[1]);
            acc8[2] = fmaf(a, w0.z, acc8[2]);
            acc8[3] = fmaf(a, w0.w, acc8[3]);
            acc8[4] = fmaf(a, w1.x, acc8[4]);
            acc8[5] = fmaf(a, w1.y, acc8[5]);
            acc8[6] = fmaf(a, w1.z, acc8[6]);
            acc8[7] = fmaf(a, w1.w, acc8[7]);
        }
        int g = base + node;
        if (g < N_NODES) {
            #pragma unroll
            for (int c = 0; c < 8; ++c)
                out[(size_t)g * 64 + c0 + c] = tanhf(acc8[c] + b4[c0 + c]);
        }
    }
}

// ---------------- host launch ----------------
extern "C" void kernel_launch(void* const* d_in, const int* in_sizes, int n_in,
                              void* d_out, int out_size) {
    const float* feat  = (const float*)d_in[0];
    const int* nbr_idx = (const int*)d_in[1];
    const int* nbr_val = (const int*)d_in[2];
    const float* wq1 = (const float*)d_in[3];
    const float* wk1 = (const float*)d_in[4];
    const float* wv1 = (const float*)d_in[5];
    const float* wo1 = (const float*)d_in[6];
    const float* bo1 = (const float*)d_in[7];
    const float* w1a = (const float*)d_in[8];
    const float* b1a = (const float*)d_in[9];
    const float* w1b = (const float*)d_in[10];
    const float* b1b = (const float*)d_in[11];
    const float* g1a = (const float*)d_in[12];
    const float* be1a = (const float*)d_in[13];
    const float* g1b = (const float*)d_in[14];
    const float* be1b = (const float*)d_in[15];
    const float* wq2 = (const float*)d_in[16];
    const float* wk2 = (const float*)d_in[17];
    const float* wv2 = (const float*)d_in[18];
    const float* wo2 = (const float*)d_in[19];
    const float* bo2 = (const float*)d_in[20];
    const float* w2a = (const float*)d_in[21];
    const float* b2a = (const float*)d_in[22];
    const float* w2b = (const float*)d_in[23];
    const float* b2b = (const float*)d_in[24];
    const float* g2a = (const float*)d_in[25];
    const float* be2a = (const float*)d_in[26];
    const float* g2b = (const float*)d_in[27];
    const float* be2b = (const float*)d_in[28];
    const float* w4 = (const float*)d_in[29];
    const float* b4 = (const float*)d_in[30];
    float* out = (float*)d_out;

    size_t smem_pre  = sizeof(SmemPre);
    size_t smem_main = sizeof(SmemMain);
    cudaFuncSetAttribute(pre_kernel,  cudaFuncAttributeMaxDynamicSharedMemorySize, (int)smem_pre);
    cudaFuncSetAttribute(main_kernel, cudaFuncAttributeMaxDynamicSharedMemorySize, (int)smem_main);

    pre_kernel<<<NTILES, NTHREADS, smem_pre>>>(feat, wk1, wv1, wk2, wv2);
    main_kernel<<<NTILES, NTHREADS, smem_main>>>(
        feat, nbr_idx, nbr_val,
        wq1, wo1, bo1, w1a, b1a, w1b, b1b, g1a, be1a, g1b, be1b,
        wq2, wo2, bo2, w2a, b2a, w2b, b2b, g2a, be2a, g2b, be2b,
        w4, b4, out);
}

// round 8
// speedup vs baseline: 2.6153x; 1.1356x over previous
#include <cuda_runtime.h>

#define N_NODES 300000
#define DIM 128
#define KNBR 5
#define EPS_LN 1e-5f
#define BLOCK 64
#define NTHREADS 256
#define NTILES ((N_NODES + BLOCK - 1) / BLOCK)
#define PAD 68      // stride (floats) of k-major transposed tiles
#define TQS 132     // stride of row-major Q buffer

typedef unsigned long long ull;

// ---------------- global scratch ----------------
__device__ float g_Kp1[(size_t)N_NODES * DIM];
__device__ float g_Vp1[(size_t)N_NODES * DIM];
__device__ float g_Kp2[(size_t)N_NODES * DIM];
__device__ float g_Vp2[(size_t)N_NODES * DIM];
__device__ float g_rowsum[N_NODES];

// ---------------- f32x2 helpers ----------------
__device__ __forceinline__ ull f2x2(float lo, float hi) {
    ull r;
    asm("mov.b64 %0, {%1, %2};" : "=l"(r) : "f"(lo), "f"(hi));
    return r;
}
__device__ __forceinline__ void ffma2(ull& d, ull a, ull b) {
    asm("fma.rn.f32x2 %0, %1, %2, %0;" : "+l"(d) : "l"(a), "l"(b));
}
__device__ __forceinline__ void unpk(ull v, float& lo, float& hi) {
    asm("mov.b64 {%0, %1}, %2;" : "=f"(lo), "=f"(hi) : "l"(v));
}
__device__ __forceinline__ unsigned sptr(const void* p) {
    return (unsigned)__cvta_generic_to_shared(p);
}
__device__ __forceinline__ void cp16(unsigned saddr, const void* g) {
    asm volatile("cp.async.cg.shared.global [%0], [%1], 16;" :: "r"(saddr), "l"(g));
}
__device__ __forceinline__ void cp_wait() {
    asm volatile("cp.async.commit_group;\n\tcp.async.wait_group 0;" ::: "memory");
}

// ---------------- shared memory layouts ----------------
struct SmemMain {
    float XT[DIM * PAD];   // residual stream, k-major          (34816 B)
    float W[64 * DIM];     // current 64x128 weight k-chunk     (32768 B)
    float S[DIM * PAD];    // scratch: Tq | AT | U | H | F      (34816 B)
    int   nidx[BLOCK * KNBR];
    int   nmask[BLOCK * KNBR];
};                          // ~102.5 KB -> 2 CTAs/SM
struct SmemPre {
    float XT[DIM * PAD];
    float W[64 * DIM];
};                          // ~66 KB -> 3 CTAs/SM

// ---------------- W chunk loaders (cp.async) ----------------
__device__ __forceinline__ void issue_chunk(const float* __restrict__ Wg,
                                            int row0, int col0, int ncols,
                                            float* __restrict__ Ws) {
    int tid = threadIdx.x;
    #pragma unroll
    for (int i = tid; i < 2048; i += NTHREADS) {   // 2048 float4
        int r  = i >> 5;
        int c4 = (i & 31) << 2;
        cp16(sptr(Ws + r * DIM + c4),
             Wg + (size_t)(row0 + r) * ncols + col0 + c4);
    }
}
__device__ __forceinline__ void stage_chunk(const float* __restrict__ Wg,
                                            int row0, int col0, int ncols,
                                            float* __restrict__ Ws) {
    __syncthreads();
    issue_chunk(Wg, row0, col0, ncols, Ws);
    cp_wait();
    __syncthreads();
}

__device__ __forceinline__ void zacc16(ull acc[16]) {
    #pragma unroll
    for (int i = 0; i < 16; ++i) acc[i] = 0ull;
}

// Warp tile 32x32, thread tile 8 rows x 4 cols.
// acc[c*4+rp] += rows (rbase+2rp, +1), col (cbase+c).
// A k-major stride PAD, Ws row-major stride DIM, K=64.
__device__ __forceinline__ void gemm64(const float* __restrict__ A,
                                       const float* __restrict__ Ws,
                                       int rbase, int cbase, ull acc[16]) {
    const float* ap = A + rbase;
    const float* wp = Ws + cbase;
    #pragma unroll 4
    for (int k = 0; k < 64; ++k) {
        ulonglong2 a01 = *(const ulonglong2*)(ap);      // rows rbase..+3
        ulonglong2 a23 = *(const ulonglong2*)(ap + 4);  // rows rbase+4..+7
        float4 w4v = *(const float4*)(wp);
        ull wx = f2x2(w4v.x, w4v.x);
        ull wy = f2x2(w4v.y, w4v.y);
        ull wz = f2x2(w4v.z, w4v.z);
        ull ww = f2x2(w4v.w, w4v.w);
        ffma2(acc[0],  a01.x, wx); ffma2(acc[1],  a01.y, wx);
        ffma2(acc[2],  a23.x, wx); ffma2(acc[3],  a23.y, wx);
        ffma2(acc[4],  a01.x, wy); ffma2(acc[5],  a01.y, wy);
        ffma2(acc[6],  a23.x, wy); ffma2(acc[7],  a23.y, wy);
        ffma2(acc[8],  a01.x, wz); ffma2(acc[9],  a01.y, wz);
        ffma2(acc[10], a23.x, wz); ffma2(acc[11], a23.y, wz);
        ffma2(acc[12], a01.x, ww); ffma2(acc[13], a01.y, ww);
        ffma2(acc[14], a23.x, ww); ffma2(acc[15], a23.y, ww);
        ap += PAD; wp += DIM;
    }
}

// store acc to k-major buffer with bias (+optional relu)
__device__ __forceinline__ void store_t(float* __restrict__ Dst,
                                        const float* __restrict__ bias,
                                        bool relu, int rbase, int cbase,
                                        const ull acc[16]) {
    #pragma unroll
    for (int c = 0; c < 4; ++c) {
        float bv = bias[cbase + c];
        #pragma unroll
        for (int rp = 0; rp < 4; ++rp) {
            float lo, hi;
            unpk(acc[c * 4 + rp], lo, hi);
            lo += bv; hi += bv;
            if (relu) { lo = fmaxf(lo, 0.f); hi = fmaxf(hi, 0.f); }
            *(float2*)(Dst + (size_t)(cbase + c) * PAD + rbase + rp * 2) =
                make_float2(lo, hi);
        }
    }
}

// LN: XT = LN(XT + UT)*gamma + beta. 2 units per thread.
__device__ __forceinline__ void ln_t(float* __restrict__ XT,
                                     const float* __restrict__ UT,
                                     const float* __restrict__ gamma,
                                     const float* __restrict__ beta) {
    int tid = threadIdx.x;
    #pragma unroll
    for (int u = 0; u < 2; ++u) {
        int idx  = tid + u * NTHREADS;
        int node = idx >> 3;
        int h    = idx & 7;
        float v[16];
        float sum = 0.f;
        #pragma unroll
        for (int i = 0; i < 16; ++i) {
            int e = h + 8 * i;
            v[i] = XT[e * PAD + node] + UT[e * PAD + node];
            sum += v[i];
        }
        sum += __shfl_xor_sync(0xffffffffu, sum, 1);
        sum += __shfl_xor_sync(0xffffffffu, sum, 2);
        sum += __shfl_xor_sync(0xffffffffu, sum, 4);
        float m = sum * (1.f / 128.f);
        float sq = 0.f;
        #pragma unroll
        for (int i = 0; i < 16; ++i) { float d = v[i] - m; sq = fmaf(d, d, sq); }
        sq += __shfl_xor_sync(0xffffffffu, sq, 1);
        sq += __shfl_xor_sync(0xffffffffu, sq, 2);
        sq += __shfl_xor_sync(0xffffffffu, sq, 4);
        float inv = rsqrtf(sq * (1.f / 128.f) + EPS_LN);
        #pragma unroll
        for (int i = 0; i < 16; ++i) {
            int e = h + 8 * i;
            XT[e * PAD + node] = (v[i] - m) * inv * gamma[e] + beta[e];
        }
    }
}

// ---------------- one transformer layer ----------------
__device__ void run_layer(SmemMain* s, int base,
                          const float* wq, const float* wo, const float* bo,
                          const float* wa, const float* ba,
                          const float* wb, const float* bb,
                          const float* ga, const float* bea,
                          const float* gb, const float* beb,
                          const float* __restrict__ Kp,
                          const float* __restrict__ Vp) {
    int tid  = threadIdx.x;
    int lane = tid & 31, warp = tid >> 5;
    int rbase = ((warp & 1) * 4 + (lane >> 3)) * 8;    // 0..56
    int cbase = (warp >> 1) * 32 + (lane & 7) * 4;     // 0..124
    float* Tq = s->S;          // row-major 64 x TQS
    ull acc[16];

    // ---- 1. Q = X @ wq (two k-halves) -> Tq ----
    zacc16(acc);
    stage_chunk(wq, 0, 0, DIM, s->W);
    gemm64(s->XT, s->W, rbase, cbase, acc);
    stage_chunk(wq, 64, 0, DIM, s->W);
    gemm64(s->XT + 64 * PAD, s->W, rbase, cbase, acc);
    #pragma unroll
    for (int c = 0; c < 4; ++c)
        #pragma unroll
        for (int rp = 0; rp < 4; ++rp) {
            float lo, hi;
            unpk(acc[c * 4 + rp], lo, hi);
            Tq[(rbase + rp * 2)     * TQS + cbase + c] = lo;
            Tq[(rbase + rp * 2 + 1) * TQS + cbase + c] = hi;
        }
    __syncthreads();   // Tq visible; W readers done

    // prefetch wo chunk 0 while attention gathers run
    issue_chunk(wo, 0, 0, DIM, s->W);

    // ---- 2. attention: 2 (node,head) units per thread ----
    float4 o2[2][4];
    #pragma unroll
    for (int u = 0; u < 2; ++u) {
        #pragma unroll
        for (int t = 0; t < 4; ++t) o2[u][t] = make_float4(0.f, 0.f, 0.f, 0.f);
        int idx  = tid + u * NTHREADS;
        int node = idx >> 3;
        int h    = idx & 7;
        int g    = base + node;
        if (g < N_NODES) {
            const float* qs = Tq + node * TQS + h * 16;
            float q[16];
            #pragma unroll
            for (int t = 0; t < 4; ++t) {
                float4 q4 = *(const float4*)(qs + t * 4);
                q[4*t] = q4.x; q[4*t+1] = q4.y; q[4*t+2] = q4.z; q[4*t+3] = q4.w;
            }
            float dots[KNBR]; bool msk[KNBR];
            #pragma unroll
            for (int j = 0; j < KNBR; ++j) {
                int mflag = s->nmask[node * KNBR + j];
                msk[j] = (mflag != 0);
                if (mflag) { dots[j] = -1e30f; continue; }
                int nb = s->nidx[node * KNBR + j];
                const float4* kp = (const float4*)(Kp + (size_t)nb * DIM + h * 16);
                float d = 0.f;
                #pragma unroll
                for (int t = 0; t < 4; ++t) {
                    float4 k4 = kp[t];
                    d = fmaf(q[4*t+0], k4.x, d);
                    d = fmaf(q[4*t+1], k4.y, d);
                    d = fmaf(q[4*t+2], k4.z, d);
                    d = fmaf(q[4*t+3], k4.w, d);
                }
                dots[j] = d * 0.25f;
            }
            float mmax = -1e30f;
            #pragma unroll
            for (int j = 0; j < KNBR; ++j) mmax = fmaxf(mmax, dots[j]);
            float e[KNBR]; float ssum = 0.f;
            #pragma unroll
            for (int j = 0; j < KNBR; ++j) {
                e[j] = msk[j] ? 0.f : __expf(dots[j] - mmax);
                ssum += e[j];
            }
            float inv = 1.f / ssum;
            #pragma unroll
            for (int j = 0; j < KNBR; ++j) {
                if (!msk[j]) {
                    int nb = s->nidx[node * KNBR + j];
                    const float4* vp = (const float4*)(Vp + (size_t)nb * DIM + h * 16);
                    float a = e[j] * inv;
                    #pragma unroll
                    for (int t = 0; t < 4; ++t) {
                        float4 v4 = vp[t];
                        o2[u][t].x = fmaf(a, v4.x, o2[u][t].x);
                        o2[u][t].y = fmaf(a, v4.y, o2[u][t].y);
                        o2[u][t].z = fmaf(a, v4.z, o2[u][t].z);
                        o2[u][t].w = fmaf(a, v4.w, o2[u][t].w);
                    }
                }
            }
        }
    }
    __syncthreads();   // everyone finished reading Tq
    #pragma unroll
    for (int u = 0; u < 2; ++u) {
        int idx  = tid + u * NTHREADS;
        int node = idx >> 3;
        int h    = idx & 7;
        #pragma unroll
        for (int t = 0; t < 4; ++t) {
            int cc = h * 16 + t * 4;
            s->S[(cc + 0) * PAD + node] = o2[u][t].x;
            s->S[(cc + 1) * PAD + node] = o2[u][t].y;
            s->S[(cc + 2) * PAD + node] = o2[u][t].z;
            s->S[(cc + 3) * PAD + node] = o2[u][t].w;
        }
    }
    cp_wait();
    __syncthreads();   // AT + wo chunk0 ready

    // ---- 3. U = attn @ wo + bo ----
    zacc16(acc);
    gemm64(s->S, s->W, rbase, cbase, acc);
    stage_chunk(wo, 64, 0, DIM, s->W);
    gemm64(s->S + 64 * PAD, s->W, rbase, cbase, acc);
    __syncthreads();                 // all done reading AT (and W)
    store_t(s->S, bo, false, rbase, cbase, acc);   // U over AT
    issue_chunk(wa, 0, 0, 256, s->W);              // prefetch wa chunk0 during LN
    __syncthreads();                 // U visible

    // ---- 4. X = LN(X + U) ----
    ln_t(s->XT, s->S, ga, bea);
    cp_wait();
    __syncthreads();                 // LN'd XT + wa chunk0 ready

    // ---- 5/6. FFN: per output-half, H-half -> accF ----
    ull accF[16]; zacc16(accF);
    #pragma unroll
    for (int h = 0; h < 2; ++h) {
        zacc16(acc);
        if (h == 1) stage_chunk(wa, 0, 128, 256, s->W);
        gemm64(s->XT, s->W, rbase, cbase, acc);
        stage_chunk(wa, 64, h * 128, 256, s->W);
        gemm64(s->XT + 64 * PAD, s->W, rbase, cbase, acc);
        __syncthreads();            // prior S readers done
        store_t(s->S, ba + h * 128, true, rbase, cbase, acc);  // H-half
        __syncthreads();
        stage_chunk(wb, h * 128, 0, DIM, s->W);
        gemm64(s->S, s->W, rbase, cbase, accF);
        stage_chunk(wb, h * 128 + 64, 0, DIM, s->W);
        gemm64(s->S + 64 * PAD, s->W, rbase, cbase, accF);
    }
    __syncthreads();                // all done reading H
    store_t(s->S, bb, false, rbase, cbase, accF);   // F
    __syncthreads();

    // ---- 7. X = LN(X + F) ----
    ln_t(s->XT, s->S, gb, beb);
    __syncthreads();
}

// ---------------- kernel 1: Kp/Vp projections + row sums ----------------
extern "C" __global__ void __launch_bounds__(NTHREADS, 3)
pre_kernel(const float* __restrict__ feat,
           const float* __restrict__ wk1, const float* __restrict__ wv1,
           const float* __restrict__ wk2, const float* __restrict__ wv2) {
    extern __shared__ char smem_raw[];
    SmemPre* s = (SmemPre*)smem_raw;
    int tid  = threadIdx.x;
    int base = blockIdx.x * BLOCK;

    #pragma unroll
    for (int i = tid; i < BLOCK * 32; i += NTHREADS) {
        int node = i >> 5;
        int k4   = (i & 31) << 2;
        int g    = base + node;
        float4 v = make_float4(0.f, 0.f, 0.f, 0.f);
        if (g < N_NODES) v = *(const float4*)(feat + (size_t)g * DIM + k4);
        s->XT[(k4 + 0) * PAD + node] = v.x;
        s->XT[(k4 + 1) * PAD + node] = v.y;
        s->XT[(k4 + 2) * PAD + node] = v.z;
        s->XT[(k4 + 3) * PAD + node] = v.w;
    }
    __syncthreads();

    {   // row sums (2 units per thread)
        #pragma unroll
        for (int u = 0; u < 2; ++u) {
            int idx  = tid + u * NTHREADS;
            int node = idx >> 3;
            int h    = idx & 7;
            float ssum = 0.f;
            #pragma unroll
            for (int i = 0; i < 16; ++i) ssum += s->XT[(h + 8 * i) * PAD + node];
            ssum += __shfl_xor_sync(0xffffffffu, ssum, 1);
            ssum += __shfl_xor_sync(0xffffffffu, ssum, 2);
            ssum += __shfl_xor_sync(0xffffffffu, ssum, 4);
            int g = base + node;
            if (h == 0 && g < N_NODES) g_rowsum[g] = ssum;
        }
    }

    int lane = tid & 31, warp = tid >> 5;
    int rbase = ((warp & 1) * 4 + (lane >> 3)) * 8;
    int cbase = (warp >> 1) * 32 + (lane & 7) * 4;
    const float* ws_in[4] = {wk1, wv1, wk2, wv2};
    float* outs[4] = {g_Kp1, g_Vp1, g_Kp2, g_Vp2};
    ull acc[16];
    #pragma unroll
    for (int w = 0; w < 4; ++w) {
        zacc16(acc);
        stage_chunk(ws_in[w], 0, 0, DIM, s->W);
        gemm64(s->XT, s->W, rbase, cbase, acc);
        stage_chunk(ws_in[w], 64, 0, DIM, s->W);
        gemm64(s->XT + 64 * PAD, s->W, rbase, cbase, acc);
        float* op = outs[w];
        #pragma unroll
        for (int rp = 0; rp < 4; ++rp) {
            float lo0, hi0, lo1, hi1, lo2, hi2, lo3, hi3;
            unpk(acc[0 * 4 + rp], lo0, hi0);
            unpk(acc[1 * 4 + rp], lo1, hi1);
            unpk(acc[2 * 4 + rp], lo2, hi2);
            unpk(acc[3 * 4 + rp], lo3, hi3);
            int g0 = base + rbase + rp * 2;
            if (g0 < N_NODES)
                *(float4*)(op + (size_t)g0 * DIM + cbase) = make_float4(lo0, lo1, lo2, lo3);
            if (g0 + 1 < N_NODES)
                *(float4*)(op + (size_t)(g0 + 1) * DIM + cbase) = make_float4(hi0, hi1, hi2, hi3);
        }
    }
}

// ---------------- kernel 2: fused 2-layer transformer + head ----------------
extern "C" __global__ void __launch_bounds__(NTHREADS, 2)
main_kernel(const float* __restrict__ feat,
            const int* __restrict__ nbr_idx,
            const int* __restrict__ nbr_valid,
            const float* wq1, const float* wo1, const float* bo1,
            const float* w1a, const float* b1a, const float* w1b, const float* b1b,
            const float* g1a, const float* be1a, const float* g1b, const float* be1b,
            const float* wq2, const float* wo2, const float* bo2,
            const float* w2a, const float* b2a, const float* w2b, const float* b2b,
            const float* g2a, const float* be2a, const float* g2b, const float* be2b,
            const float* w4, const float* b4,
            float* __restrict__ out) {
    extern __shared__ char smem_raw[];
    SmemMain* s = (SmemMain*)smem_raw;
    int tid  = threadIdx.x;
    int base = blockIdx.x * BLOCK;

    #pragma unroll
    for (int i = tid; i < BLOCK * 32; i += NTHREADS) {
        int node = i >> 5;
        int k4   = (i & 31) << 2;
        int g    = base + node;
        float4 v = make_float4(0.f, 0.f, 0.f, 0.f);
        if (g < N_NODES) v = *(const float4*)(feat + (size_t)g * DIM + k4);
        s->XT[(k4 + 0) * PAD + node] = v.x;
        s->XT[(k4 + 1) * PAD + node] = v.y;
        s->XT[(k4 + 2) * PAD + node] = v.z;
        s->XT[(k4 + 3) * PAD + node] = v.w;
    }
    for (int i = tid; i < BLOCK * KNBR; i += NTHREADS) {
        int node = i / KNBR;
        int j    = i - node * KNBR;
        int g    = base + node;
        int idx = 0, mflag = 1;
        if (g < N_NODES) {
            idx = nbr_idx[(size_t)g * KNBR + j];
            int valid = nbr_valid[(size_t)g * KNBR + j];   // nonzero = true
            mflag = (valid == 0) || (g_rowsum[idx] == 0.f);
        }
        s->nidx[i]  = idx;
        s->nmask[i] = mflag;
    }
    __syncthreads();

    run_layer(s, base, wq1, wo1, bo1, w1a, b1a, w1b, b1b,
              g1a, be1a, g1b, be1b, g_Kp1, g_Vp1);
    run_layer(s, base, wq2, wo2, bo2, w2a, b2a, w2b, b2b,
              g2a, be2a, g2b, be2b, g_Kp2, g_Vp2);

    // ---- head: out = tanh(X @ w4 + b4), w4: 128x64 ----
    __syncthreads();
    {
        #pragma unroll
        for (int i = tid; i < 2048; i += NTHREADS) {   // 2048 float4
            int r  = i >> 4;
            int c4 = (i & 15) << 2;
            cp16(sptr(s->W + r * 64 + c4), w4 + r * 64 + c4);
        }
        cp_wait();
    }
    __syncthreads();
    #pragma unroll
    for (int u = 0; u < 2; ++u) {
        int idx  = tid + u * NTHREADS;
        int node = idx >> 3;
        int c0   = (idx & 7) * 8;
        float acc8[8];
        #pragma unroll
        for (int c = 0; c < 8; ++c) acc8[c] = 0.f;
        #pragma unroll 4
        for (int kk = 0; kk < DIM; ++kk) {
            float a = s->XT[kk * PAD + node];
            float4 w0 = *(const float4*)(s->W + kk * 64 + c0);
            float4 w1 = *(const float4*)(s->W + kk * 64 + c0 + 4);
            acc8[0] = fmaf(a, w0.x, acc8[0]);
            acc8[1] = fmaf(a, w0.y, acc8[1]);
            acc8[2] = fmaf(a, w0.z, acc8[2]);
            acc8[3] = fmaf(a, w0.w, acc8[3]);
            acc8[4] = fmaf(a, w1.x, acc8[4]);
            acc8[5] = fmaf(a, w1.y, acc8[5]);
            acc8[6] = fmaf(a, w1.z, acc8[6]);
            acc8[7] = fmaf(a, w1.w, acc8[7]);
        }
        int g = base + node;
        if (g < N_NODES) {
            #pragma unroll
            for (int c = 0; c < 8; ++c)
                out[(size_t)g * 64 + c0 + c] = tanhf(acc8[c] + b4[c0 + c]);
        }
    }
}

// ---------------- host launch ----------------
extern "C" void kernel_launch(void* const* d_in, const int* in_sizes, int n_in,
                              void* d_out, int out_size) {
    const float* feat  = (const float*)d_in[0];
    const int* nbr_idx = (const int*)d_in[1];
    const int* nbr_val = (const int*)d_in[2];
    const float* wq1 = (const float*)d_in[3];
    const float* wk1 = (const float*)d_in[4];
    const float* wv1 = (const float*)d_in[5];
    const float* wo1 = (const float*)d_in[6];
    const float* bo1 = (const float*)d_in[7];
    const float* w1a = (const float*)d_in[8];
    const float* b1a = (const float*)d_in[9];
    const float* w1b = (const float*)d_in[10];
    const float* b1b = (const float*)d_in[11];
    const float* g1a = (const float*)d_in[12];
    const float* be1a = (const float*)d_in[13];
    const float* g1b = (const float*)d_in[14];
    const float* be1b = (const float*)d_in[15];
    const float* wq2 = (const float*)d_in[16];
    const float* wk2 = (const float*)d_in[17];
    const float* wv2 = (const float*)d_in[18];
    const float* wo2 = (const float*)d_in[19];
    const float* bo2 = (const float*)d_in[20];
    const float* w2a = (const float*)d_in[21];
    const float* b2a = (const float*)d_in[22];
    const float* w2b = (const float*)d_in[23];
    const float* b2b = (const float*)d_in[24];
    const float* g2a = (const float*)d_in[25];
    const float* be2a = (const float*)d_in[26];
    const float* g2b = (const float*)d_in[27];
    const float* be2b = (const float*)d_in[28];
    const float* w4 = (const float*)d_in[29];
    const float* b4 = (const float*)d_in[30];
    float* out = (float*)d_out;

    size_t smem_pre  = sizeof(SmemPre);
    size_t smem_main = sizeof(SmemMain);
    cudaFuncSetAttribute(pre_kernel,  cudaFuncAttributeMaxDynamicSharedMemorySize, (int)smem_pre);
    cudaFuncSetAttribute(main_kernel, cudaFuncAttributeMaxDynamicSharedMemorySize, (int)smem_main);

    pre_kernel<<<NTILES, NTHREADS, smem_pre>>>(feat, wk1, wv1, wk2, wv2);
    main_kernel<<<NTILES, NTHREADS, smem_main>>>(
        feat, nbr_idx, nbr_val,
        wq1, wo1, bo1, w1a, b1a, w1b, b1b, g1a, be1a, g1b, be1b,
        wq2, wo2, bo2, w2a, b2a, w2b, b2b, g2a, be2a, g2b, be2b,
        w4, b4, out);
}